// round 13
// baseline (speedup 1.0000x reference)
#include <cuda_runtime.h>
#include <cuda_fp16.h>
#include <cstdint>
#include <cstdio>

// Problem constants
static constexpr int CB = 4;        // batch
static constexpr int CT = 1024;     // seq len
static constexpr int CD = 1024;     // d_model
static constexpr int CH = 16;       // heads
static constexpr int CHS = 64;      // head size
static constexpr int CL = 4;        // layers
static constexpr int CFF = 4096;    // ffn dim
static constexpr int CV = 32000;    // vocab
static constexpr int CM = CB * CT;  // 4096 rows

// ---------------- scratch (device globals; no allocation allowed) ----------
__device__ float  g_x[CM * CD];               // residual stream (fp32)
__device__ __half g_h[CM * CD];               // ln output / attn-out (fp16)
__device__ __half g_qkv[CM * 3 * CD];         // qkv activations (fp16)
__device__ __half g_act[CM * CFF];            // ffn activation (fp16)
__device__ __half g_wpack[CL * CD * 3 * CD];  // packed qkv weights [k][n]
__device__ __half g_wproj_h[CL * CD * CD];
__device__ __half g_w1_h[CL * CD * CFF];
__device__ __half g_w2_h[CL * CFF * CD];
__device__ __half g_wout_h[CD * CV];

// ---------------- helpers ---------------------------------------------------
__device__ __forceinline__ uint32_t pack_h2(float lo, float hi) {
    __half2 h = __floats2half2_rn(lo, hi);
    return *(uint32_t*)&h;
}

__device__ __forceinline__ void mma_f16(float* c, const uint32_t* a, const uint32_t* b) {
    asm volatile(
        "mma.sync.aligned.m16n8k16.row.col.f32.f16.f16.f32 "
        "{%0,%1,%2,%3}, {%4,%5,%6,%7}, {%8,%9}, {%0,%1,%2,%3};"
        : "+f"(c[0]), "+f"(c[1]), "+f"(c[2]), "+f"(c[3])
        : "r"(a[0]), "r"(a[1]), "r"(a[2]), "r"(a[3]), "r"(b[0]), "r"(b[1]));
}

__device__ __forceinline__ void ldsm_x4(uint32_t* r, uint32_t a) {
    asm volatile(
        "ldmatrix.sync.aligned.m8n8.x4.shared.b16 {%0,%1,%2,%3}, [%4];"
        : "=r"(r[0]), "=r"(r[1]), "=r"(r[2]), "=r"(r[3]) : "r"(a));
}
__device__ __forceinline__ void ldsm_x2(uint32_t* r, uint32_t a) {
    asm volatile(
        "ldmatrix.sync.aligned.m8n8.x2.shared.b16 {%0,%1}, [%2];"
        : "=r"(r[0]), "=r"(r[1]) : "r"(a));
}
__device__ __forceinline__ void ldsm_x2t(uint32_t* r, uint32_t a) {
    asm volatile(
        "ldmatrix.sync.aligned.m8n8.x2.trans.shared.b16 {%0,%1}, [%2];"
        : "=r"(r[0]), "=r"(r[1]) : "r"(a));
}
__device__ __forceinline__ void ldsm_x4t(uint32_t* r, uint32_t a) {
    asm volatile(
        "ldmatrix.sync.aligned.m8n8.x4.trans.shared.b16 {%0,%1,%2,%3}, [%4];"
        : "=r"(r[0]), "=r"(r[1]), "=r"(r[2]), "=r"(r[3]) : "r"(a));
}

__device__ __forceinline__ void cp_async16(uint32_t dst_smem, const void* src) {
    asm volatile("cp.async.cg.shared.global [%0], [%1], 16;" ::
                 "r"(dst_smem), "l"(src));
}
__device__ __forceinline__ void cp_commit() {
    asm volatile("cp.async.commit_group;");
}
template <int N>
__device__ __forceinline__ void cp_wait() {
    asm volatile("cp.async.wait_group %0;" :: "n"(N));
}

// ---------------- embedding (fp32 residual) --------------------------------
__global__ void embed_kernel(const int* __restrict__ ids,
                             const float* __restrict__ tok_emb,
                             const float* __restrict__ pos_emb,
                             float* __restrict__ x) {
    int idx = blockIdx.x * blockDim.x + threadIdx.x;
    if (idx >= CM * CD) return;
    int d = idx % CD;
    int bt = idx / CD;
    int t = bt % CT;
    x[idx] = tok_emb[(size_t)ids[bt] * CD + d] + pos_emb[t * CD + d];
}

// ---------------- qkv weight pack (+fp16 cvt): -> (L, D, 3*H*HS) -----------
__global__ void pack_qkv_kernel(const float* __restrict__ wq,
                                const float* __restrict__ wk,
                                const float* __restrict__ wv,
                                __half* __restrict__ wp) {
    const int PER = CL * CH * CD * CHS;
    int idx = blockIdx.x * blockDim.x + threadIdx.x;
    if (idx >= 3 * PER) return;
    int which = idx / PER;
    int r = idx % PER;
    int e = r % CHS;
    int d = (r / CHS) % CD;
    int h = (r / (CHS * CD)) % CH;
    int l = r / (CHS * CD * CH);
    const float* src = (which == 0) ? wq : (which == 1) ? wk : wv;
    wp[((size_t)l * CD + d) * (3 * CD) + which * CD + h * CHS + e] =
        __float2half_rn(src[r]);
}

// ---------------- merged weight fp16 convert (2 arrays per launch) ---------
__global__ void cvt_copy2_kernel(const float* __restrict__ s1,
                                 __half* __restrict__ d1, int n1,
                                 const float* __restrict__ s2,
                                 __half* __restrict__ d2, int n2) {
    int idx = blockIdx.x * blockDim.x + threadIdx.x;
    int q1 = n1 >> 2;
    if (idx < q1) {
        float4 v = ((const float4*)s1)[idx];
        uint2 o = make_uint2(pack_h2(v.x, v.y), pack_h2(v.z, v.w));
        *(uint2*)&d1[(size_t)idx * 4] = o;
    } else {
        int i2 = idx - q1;
        if (i2 * 4 < n2) {
            float4 v = ((const float4*)s2)[i2];
            uint2 o = make_uint2(pack_h2(v.x, v.y), pack_h2(v.z, v.w));
            *(uint2*)&d2[(size_t)i2 * 4] = o;
        }
    }
}

// ---------------- layernorm (fp16 output) -----------------------------------
__device__ __forceinline__ float warp_sum(float v) {
    #pragma unroll
    for (int o = 16; o; o >>= 1) v += __shfl_xor_sync(0xffffffffu, v, o);
    return v;
}

__global__ void ln_kernel(const float* __restrict__ x,
                          const float* __restrict__ g,
                          const float* __restrict__ b,
                          __half* __restrict__ out) {
    int row = blockIdx.x;
    int tid = threadIdx.x;
    const float4* xr = (const float4*)(x + (size_t)row * CD);
    float4 v = xr[tid];
    float s = v.x + v.y + v.z + v.w;
    float s2 = v.x * v.x + v.y * v.y + v.z * v.z + v.w * v.w;
    s = warp_sum(s);
    s2 = warp_sum(s2);
    __shared__ float shs[8], shs2[8];
    int w = tid >> 5, lane = tid & 31;
    if (lane == 0) { shs[w] = s; shs2[w] = s2; }
    __syncthreads();
    if (tid == 0) {
        float a = 0.f, a2 = 0.f;
        #pragma unroll
        for (int i = 0; i < 8; i++) { a += shs[i]; a2 += shs2[i]; }
        shs[0] = a; shs2[0] = a2;
    }
    __syncthreads();
    float mean = shs[0] * (1.f / CD);
    float var = shs2[0] * (1.f / CD) - mean * mean;
    float rstd = rsqrtf(var + 1e-5f);
    float4 gv = ((const float4*)g)[tid];
    float4 bv = ((const float4*)b)[tid];
    uint2 o = make_uint2(
        pack_h2((v.x - mean) * rstd * gv.x + bv.x, (v.y - mean) * rstd * gv.y + bv.y),
        pack_h2((v.z - mean) * rstd * gv.z + bv.z, (v.w - mean) * rstd * gv.w + bv.w));
    *(uint2*)&out[(size_t)row * CD + tid * 4] = o;
}

// ---------------- FP16 tensor-core GEMM (BK=64, x4t B loads) ----------------
// C[M,N] = A[M,K] @ B[K,N] (+bias) (+res) (relu); C fp32 or fp16.
// Block 128x128, BK=64, 3-stage cp.async, 8 warps (2Mx4N), warp tile 64x32.
// A: ldmatrix.x4; B: ldmatrix.x4.trans (2 n-tiles per instr).
// Grid: x = M-tile (fastest) for cross-M L2 reuse of B.
static constexpr int GSTAGES = 3;
static constexpr int A_PH = 72;            // halfs per A row (64 + 8 pad)
static constexpr int B_PH = 136;           // halfs per B row (128 + 8 pad)
static constexpr int G_ASZ = 128 * A_PH;   // halfs per A stage
static constexpr int G_BSZ = 64 * B_PH;    // halfs per B stage
static constexpr int GEMM_SMEM = GSTAGES * (G_ASZ + G_BSZ) * 2;  // 107520 B

template <bool HAS_BIAS, bool HAS_RES, bool RELU, bool OUT_HALF>
__global__ __launch_bounds__(256, 2)
void f16_gemm(const __half* __restrict__ A, const __half* __restrict__ B,
              void* __restrict__ Cv, const float* __restrict__ bias,
              const float* __restrict__ res, int M, int N, int K) {
    extern __shared__ char smraw[];
    __half* As = (__half*)smraw;
    __half* Bs = As + GSTAGES * G_ASZ;

    const int tid = threadIdx.x;
    const int lane = tid & 31;
    const int warp = tid >> 5;
    const int wm = warp & 1;
    const int wn = warp >> 1;
    const int bm = blockIdx.x * 128;
    const int bn = blockIdx.y * 128;

    const int g = lane >> 2;
    const int tg = lane & 3;

    const uint32_t as_base = (uint32_t)__cvta_generic_to_shared(As);
    const uint32_t bs_base = (uint32_t)__cvta_generic_to_shared(Bs);

    // fragment base addresses (bytes)
    const uint32_t a_frag = as_base +
        (uint32_t)(((wm * 64 + (lane & 15)) * A_PH) + ((lane & 16) >> 1)) * 2;
    // x4.trans B: lane provides row kk+(lane&15), col wn*32 + 8*(lane>>4)
    const uint32_t b_frag = bs_base +
        (uint32_t)((lane & 15) * B_PH + wn * 32 + ((lane >> 4) << 3)) * 2;

    auto load_stage = [&](int s, int k0) {
        #pragma unroll
        for (int it = 0; it < 4; it++) {
            int idx = tid + it * 256;
            int row = idx >> 3, c = (idx & 7) * 8;
            cp_async16(as_base + (uint32_t)(s * G_ASZ + row * A_PH + c) * 2,
                       &A[(size_t)(bm + row) * K + k0 + c]);
        }
        #pragma unroll
        for (int it = 0; it < 4; it++) {
            int idx = tid + it * 256;
            int row = idx >> 4, c = (idx & 15) * 8;
            cp_async16(bs_base + (uint32_t)(s * G_BSZ + row * B_PH + c) * 2,
                       &B[(size_t)(k0 + row) * N + bn + c]);
        }
    };

    float acc[4][4][4];
    #pragma unroll
    for (int i = 0; i < 4; i++)
        #pragma unroll
        for (int j = 0; j < 4; j++)
            #pragma unroll
            for (int k = 0; k < 4; k++) acc[i][j][k] = 0.f;

    const int nk = K >> 6;
    #pragma unroll
    for (int s = 0; s < GSTAGES - 1; s++) {
        load_stage(s, s * 64);
        cp_commit();
    }
    cp_wait<GSTAGES - 2>();
    __syncthreads();

    for (int ks = 0; ks < nk; ks++) {
        const int buf = ks % GSTAGES;
        const int pre = ks + GSTAGES - 1;
        if (pre < nk) load_stage(pre % GSTAGES, pre * 64);
        cp_commit();

        const uint32_t a_st = a_frag + (uint32_t)(buf * G_ASZ) * 2;
        const uint32_t b_st = b_frag + (uint32_t)(buf * G_BSZ) * 2;
        #pragma unroll
        for (int kk = 0; kk < 64; kk += 16) {
            uint32_t af[4][4], bf[4][2];
            #pragma unroll
            for (int mi = 0; mi < 4; mi++)
                ldsm_x4(af[mi], a_st + (uint32_t)(mi * 16 * A_PH + kk) * 2);
            #pragma unroll
            for (int pr = 0; pr < 2; pr++) {
                uint32_t t[4];
                ldsm_x4t(t, b_st + (uint32_t)(kk * B_PH + pr * 16) * 2);
                bf[2 * pr][0] = t[0]; bf[2 * pr][1] = t[1];
                bf[2 * pr + 1][0] = t[2]; bf[2 * pr + 1][1] = t[3];
            }
            #pragma unroll
            for (int mi = 0; mi < 4; mi++)
                #pragma unroll
                for (int ni = 0; ni < 4; ni++)
                    mma_f16(acc[mi][ni], af[mi], bf[ni]);
        }

        cp_wait<GSTAGES - 2>();
        __syncthreads();
    }

    // epilogue
    #pragma unroll
    for (int mi = 0; mi < 4; mi++) {
        #pragma unroll
        for (int ni = 0; ni < 4; ni++) {
            const int col = bn + wn * 32 + ni * 8 + 2 * tg;
            #pragma unroll
            for (int half_ = 0; half_ < 2; half_++) {
                const int row = bm + wm * 64 + mi * 16 + g + half_ * 8;
                float vx = acc[mi][ni][half_ * 2 + 0];
                float vy = acc[mi][ni][half_ * 2 + 1];
                if (HAS_BIAS) { vx += bias[col]; vy += bias[col + 1]; }
                if (HAS_RES) {
                    const float2 r = *(const float2*)&res[(size_t)row * N + col];
                    vx += r.x; vy += r.y;
                }
                if (RELU) { vx = fmaxf(vx, 0.f); vy = fmaxf(vy, 0.f); }
                if (OUT_HALF) {
                    *(uint32_t*)&((__half*)Cv)[(size_t)row * N + col] = pack_h2(vx, vy);
                } else {
                    *(float2*)&((float*)Cv)[(size_t)row * N + col] = make_float2(vx, vy);
                }
            }
        }
    }
}

// ---------------- fp16 tensor-core flash attention --------------------------
static constexpr int AQP = 72;
static constexpr int ATT_SMEM = (128 + 64 + 64) * AQP * 2;

__global__ __launch_bounds__(256, 2)
void attn_f16_kernel(const __half* __restrict__ qkv, __half* __restrict__ out) {
    extern __shared__ char smraw[];
    __half* Qs = (__half*)smraw;          // [128][AQP]
    __half* Ks = Qs + 128 * AQP;          // [64][AQP]
    __half* Vs = Ks + 64 * AQP;           // [64][AQP]

    const int qt = blockIdx.x;
    const int h = blockIdx.y;
    const int b = blockIdx.z;
    const int tid = threadIdx.x;
    const int lane = tid & 31;
    const int warp = tid >> 5;
    const int g = lane >> 2;
    const int tg = lane & 3;
    const int rw = warp * 16;

    const size_t base = (size_t)(b * CT) * (3 * CD) + h * CHS;

    #pragma unroll
    for (int it = 0; it < 4; it++) {
        int idx = tid + it * 256;
        int r = idx >> 3, c = (idx & 7) * 8;
        *(uint4*)&Qs[r * AQP + c] =
            *(const uint4*)&qkv[base + (size_t)(qt * 128 + r) * (3 * CD) + c];
    }

    const uint32_t qs_u = (uint32_t)__cvta_generic_to_shared(Qs);
    const uint32_t ks_u = (uint32_t)__cvta_generic_to_shared(Ks);
    const uint32_t vs_u = (uint32_t)__cvta_generic_to_shared(Vs);

    const uint32_t q_frag =
        qs_u + (uint32_t)(((rw + (lane & 15)) * AQP) + ((lane & 16) >> 1)) * 2;
    const uint32_t k_fragbase =
        ks_u + (uint32_t)((lane & 7) * AQP + (lane & 8)) * 2;
    const uint32_t v_fragbase =
        vs_u + (uint32_t)((lane & 15) * AQP) * 2;

    const float scale = 0.03125f;  // 1/sqrt(1024): reference scales by d_model
    const int rowq0 = qt * 128 + rw + g;
    const int rowq1 = rowq0 + 8;

    float m0 = -1e30f, m1 = -1e30f, l0 = 0.f, l1 = 0.f;
    float acc_o[8][4];
    #pragma unroll
    for (int i = 0; i < 8; i++)
        #pragma unroll
        for (int j = 0; j < 4; j++) acc_o[i][j] = 0.f;

    const int nst = 2 * qt + 2;
    for (int st = 0; st < nst; st++) {
        __syncthreads();
        #pragma unroll
        for (int it = 0; it < 2; it++) {
            int idx = tid + it * 256;
            int r = idx >> 3, c = (idx & 7) * 8;
            size_t ga = base + (size_t)(st * 64 + r) * (3 * CD);
            *(uint4*)&Ks[r * AQP + c] = *(const uint4*)&qkv[ga + CD + c];
            *(uint4*)&Vs[r * AQP + c] = *(const uint4*)&qkv[ga + 2 * CD + c];
        }
        __syncthreads();

        float acc_s[8][4];
        #pragma unroll
        for (int i = 0; i < 8; i++)
            #pragma unroll
            for (int j = 0; j < 4; j++) acc_s[i][j] = 0.f;
        #pragma unroll
        for (int kk = 0; kk < 64; kk += 16) {
            uint32_t af[4];
            ldsm_x4(af, q_frag + (uint32_t)kk * 2);
            #pragma unroll
            for (int ni = 0; ni < 8; ni++) {
                uint32_t bf[2];
                ldsm_x2(bf, k_fragbase + (uint32_t)(ni * 8 * AQP + kk) * 2);
                mma_f16(acc_s[ni], af, bf);
            }
        }

        float rmax0 = -1e30f, rmax1 = -1e30f;
        #pragma unroll
        for (int ni = 0; ni < 8; ni++) {
            const int c0 = st * 64 + ni * 8 + 2 * tg;
            float v0 = acc_s[ni][0] * scale; if (c0 > rowq0) v0 = -1e30f;
            float v1 = acc_s[ni][1] * scale; if (c0 + 1 > rowq0) v1 = -1e30f;
            float v2 = acc_s[ni][2] * scale; if (c0 > rowq1) v2 = -1e30f;
            float v3 = acc_s[ni][3] * scale; if (c0 + 1 > rowq1) v3 = -1e30f;
            acc_s[ni][0] = v0; acc_s[ni][1] = v1;
            acc_s[ni][2] = v2; acc_s[ni][3] = v3;
            rmax0 = fmaxf(rmax0, fmaxf(v0, v1));
            rmax1 = fmaxf(rmax1, fmaxf(v2, v3));
        }
        #pragma unroll
        for (int off = 1; off < 4; off <<= 1) {
            rmax0 = fmaxf(rmax0, __shfl_xor_sync(0xffffffffu, rmax0, off));
            rmax1 = fmaxf(rmax1, __shfl_xor_sync(0xffffffffu, rmax1, off));
        }

        const float mn0 = fmaxf(m0, rmax0), mn1 = fmaxf(m1, rmax1);
        const float sc0 = __expf(m0 - mn0), sc1 = __expf(m1 - mn1);
        m0 = mn0; m1 = mn1;
        float rs0 = 0.f, rs1 = 0.f;
        #pragma unroll
        for (int ni = 0; ni < 8; ni++) {
            float p0 = __expf(acc_s[ni][0] - mn0);
            float p1 = __expf(acc_s[ni][1] - mn0);
            float p2 = __expf(acc_s[ni][2] - mn1);
            float p3 = __expf(acc_s[ni][3] - mn1);
            acc_s[ni][0] = p0; acc_s[ni][1] = p1;
            acc_s[ni][2] = p2; acc_s[ni][3] = p3;
            rs0 += p0 + p1; rs1 += p2 + p3;
        }
        #pragma unroll
        for (int off = 1; off < 4; off <<= 1) {
            rs0 += __shfl_xor_sync(0xffffffffu, rs0, off);
            rs1 += __shfl_xor_sync(0xffffffffu, rs1, off);
        }
        l0 = l0 * sc0 + rs0;
        l1 = l1 * sc1 + rs1;
        #pragma unroll
        for (int ni = 0; ni < 8; ni++) {
            acc_o[ni][0] *= sc0; acc_o[ni][1] *= sc0;
            acc_o[ni][2] *= sc1; acc_o[ni][3] *= sc1;
        }

        #pragma unroll
        for (int j = 0; j < 4; j++) {
            uint32_t pa[4];
            pa[0] = pack_h2(acc_s[2 * j][0], acc_s[2 * j][1]);
            pa[1] = pack_h2(acc_s[2 * j][2], acc_s[2 * j][3]);
            pa[2] = pack_h2(acc_s[2 * j + 1][0], acc_s[2 * j + 1][1]);
            pa[3] = pack_h2(acc_s[2 * j + 1][2], acc_s[2 * j + 1][3]);
            #pragma unroll
            for (int ni = 0; ni < 8; ni++) {
                uint32_t bf[2];
                ldsm_x2t(bf, v_fragbase + (uint32_t)(j * 16 * AQP + ni * 8) * 2);
                mma_f16(acc_o[ni], pa, bf);
            }
        }
    }

    const float inv0 = 1.f / l0, inv1 = 1.f / l1;
    #pragma unroll
    for (int ni = 0; ni < 8; ni++) {
        const int col = h * CHS + ni * 8 + 2 * tg;
        *(uint32_t*)&out[(size_t)(b * CT + rowq0) * CD + col] =
            pack_h2(acc_o[ni][0] * inv0, acc_o[ni][1] * inv0);
        *(uint32_t*)&out[(size_t)(b * CT + rowq1) * CD + col] =
            pack_h2(acc_o[ni][2] * inv1, acc_o[ni][3] * inv1);
    }
}

// ---------------- host orchestration --------------------------------------
extern "C" void kernel_launch(void* const* d_in, const int* in_sizes, int n_in,
                              void* d_out, int out_size) {
    const int*   token_ids = (const int*)d_in[0];
    const float* tok_emb   = (const float*)d_in[1];
    const float* pos_emb   = (const float*)d_in[2];
    const float* wq        = (const float*)d_in[3];
    const float* wk        = (const float*)d_in[4];
    const float* wv        = (const float*)d_in[5];
    const float* w_proj    = (const float*)d_in[6];
    const float* b_proj    = (const float*)d_in[7];
    const float* ln1_g     = (const float*)d_in[8];
    const float* ln1_b     = (const float*)d_in[9];
    const float* ln2_g     = (const float*)d_in[10];
    const float* ln2_b     = (const float*)d_in[11];
    const float* w1        = (const float*)d_in[12];
    const float* b1        = (const float*)d_in[13];
    const float* w2        = (const float*)d_in[14];
    const float* b2        = (const float*)d_in[15];
    const float* lnf_g     = (const float*)d_in[16];
    const float* lnf_b     = (const float*)d_in[17];
    const float* w_out     = (const float*)d_in[18];
    const float* b_out     = (const float*)d_in[19];
    float* out = (float*)d_out;

    float* x;
    __half *hbuf, *qkv, *act, *wpack, *wproj_h, *w1_h, *w2_h, *wout_h;
    cudaGetSymbolAddress((void**)&x, g_x);
    cudaGetSymbolAddress((void**)&hbuf, g_h);
    cudaGetSymbolAddress((void**)&qkv, g_qkv);
    cudaGetSymbolAddress((void**)&act, g_act);
    cudaGetSymbolAddress((void**)&wpack, g_wpack);
    cudaGetSymbolAddress((void**)&wproj_h, g_wproj_h);
    cudaGetSymbolAddress((void**)&w1_h, g_w1_h);
    cudaGetSymbolAddress((void**)&w2_h, g_w2_h);
    cudaGetSymbolAddress((void**)&wout_h, g_wout_h);

    cudaFuncSetAttribute(attn_f16_kernel,
                         cudaFuncAttributeMaxDynamicSharedMemorySize, ATT_SMEM);
    cudaFuncSetAttribute(f16_gemm<false, false, false, true>,
                         cudaFuncAttributeMaxDynamicSharedMemorySize, GEMM_SMEM);
    cudaFuncSetAttribute(f16_gemm<true, true, false, false>,
                         cudaFuncAttributeMaxDynamicSharedMemorySize, GEMM_SMEM);
    cudaFuncSetAttribute(f16_gemm<true, false, true, true>,
                         cudaFuncAttributeMaxDynamicSharedMemorySize, GEMM_SMEM);
    cudaFuncSetAttribute(f16_gemm<true, false, false, false>,
                         cudaFuncAttributeMaxDynamicSharedMemorySize, GEMM_SMEM);

    // 1) embedding
    {
        int n = CM * CD;
        embed_kernel<<<(n + 255) / 256, 256>>>(token_ids, tok_emb, pos_emb, x);
    }
    // 2) weight prep (fp16 convert)
    {
        int n = 3 * CL * CH * CD * CHS;
        pack_qkv_kernel<<<(n + 255) / 256, 256>>>(wq, wk, wv, wpack);
    }
    {
        int n1 = CL * CD * CD, n2 = CL * CD * CFF;
        int tot = (n1 + n2) / 4;
        cvt_copy2_kernel<<<(tot + 255) / 256, 256>>>(w_proj, wproj_h, n1,
                                                     w1, w1_h, n2);
        int n3 = CL * CFF * CD, n4 = CD * CV;
        tot = (n3 + n4) / 4;
        cvt_copy2_kernel<<<(tot + 255) / 256, 256>>>(w2, w2_h, n3,
                                                     w_out, wout_h, n4);
    }

    dim3 attn_grid(CT / 128, CH, CB);

    for (int l = 0; l < CL; l++) {
        // ln1 -> h (fp16)
        ln_kernel<<<CM, 256>>>(x, ln1_g + l * CD, ln1_b + l * CD, hbuf);
        // qkv = h @ wpack[l]   (4096 x 3072 x 1024), fp16 out
        {
            dim3 grid(CM / 128, 3 * CD / 128);
            f16_gemm<false, false, false, true><<<grid, 256, GEMM_SMEM>>>(
                hbuf, wpack + (size_t)l * CD * 3 * CD, qkv, nullptr, nullptr,
                CM, 3 * CD, CD);
        }
        // attention -> h (fp16 flash)
        attn_f16_kernel<<<attn_grid, 256, ATT_SMEM>>>(qkv, hbuf);
        // x = x + h @ w_proj[l] + b_proj[l]  (fp32 out + residual)
        {
            dim3 grid(CM / 128, CD / 128);
            f16_gemm<true, true, false, false><<<grid, 256, GEMM_SMEM>>>(
                hbuf, wproj_h + (size_t)l * CD * CD, x, b_proj + l * CD, x,
                CM, CD, CD);
        }
        // ln2 -> h (fp16)
        ln_kernel<<<CM, 256>>>(x, ln2_g + l * CD, ln2_b + l * CD, hbuf);
        // act = relu(h @ w1[l] + b1[l])  (fp16 out)
        {
            dim3 grid(CM / 128, CFF / 128);
            f16_gemm<true, false, true, true><<<grid, 256, GEMM_SMEM>>>(
                hbuf, w1_h + (size_t)l * CD * CFF, act, b1 + (size_t)l * CFF, nullptr,
                CM, CFF, CD);
        }
        // x = x + act @ w2[l] + b2[l]  (fp32 out + residual)
        {
            dim3 grid(CM / 128, CD / 128);
            f16_gemm<true, true, false, false><<<grid, 256, GEMM_SMEM>>>(
                act, w2_h + (size_t)l * CFF * CD, x, b2 + l * CD, x,
                CM, CD, CFF);
        }
    }

    // final ln -> h (fp16)
    ln_kernel<<<CM, 256>>>(x, lnf_g, lnf_b, hbuf);
    // logits = h @ w_out + b_out   (4096 x 32000 x 1024), fp32 out
    {
        dim3 grid(CM / 128, CV / 128);
        f16_gemm<true, false, false, false><<<grid, 256, GEMM_SMEM>>>(
            hbuf, wout_h, out, b_out, nullptr, CM, CV, CD);
    }
}

// round 15
// speedup vs baseline: 1.5258x; 1.5258x over previous
#include <cuda_runtime.h>
#include <cuda_fp16.h>
#include <cstdint>
#include <cstdio>

// Problem constants
static constexpr int CB = 4;        // batch
static constexpr int CT = 1024;     // seq len
static constexpr int CD = 1024;     // d_model
static constexpr int CH = 16;       // heads
static constexpr int CHS = 64;      // head size
static constexpr int CL = 4;        // layers
static constexpr int CFF = 4096;    // ffn dim
static constexpr int CV = 32000;    // vocab
static constexpr int CM = CB * CT;  // 4096 rows

// ---------------- scratch (device globals; no allocation allowed) ----------
__device__ float  g_x[CM * CD];               // residual stream (fp32)
__device__ __half g_h[CM * CD];               // ln output / attn-out (fp16)
__device__ __half g_qkv[CM * 3 * CD];         // qkv activations (fp16)
__device__ __half g_act[CM * CFF];            // ffn activation (fp16)
__device__ __half g_wpack[CL * CD * 3 * CD];  // packed qkv weights [k][n]
__device__ __half g_wproj_h[CL * CD * CD];
__device__ __half g_w1_h[CL * CD * CFF];
__device__ __half g_w2_h[CL * CFF * CD];
__device__ __half g_wout_h[CD * CV];

// ---------------- helpers ---------------------------------------------------
__device__ __forceinline__ uint32_t pack_h2(float lo, float hi) {
    __half2 h = __floats2half2_rn(lo, hi);
    return *(uint32_t*)&h;
}

__device__ __forceinline__ void mma_f16(float* c, const uint32_t* a, const uint32_t* b) {
    asm volatile(
        "mma.sync.aligned.m16n8k16.row.col.f32.f16.f16.f32 "
        "{%0,%1,%2,%3}, {%4,%5,%6,%7}, {%8,%9}, {%0,%1,%2,%3};"
        : "+f"(c[0]), "+f"(c[1]), "+f"(c[2]), "+f"(c[3])
        : "r"(a[0]), "r"(a[1]), "r"(a[2]), "r"(a[3]), "r"(b[0]), "r"(b[1]));
}

__device__ __forceinline__ void ldsm_x4(uint32_t* r, uint32_t a) {
    asm volatile(
        "ldmatrix.sync.aligned.m8n8.x4.shared.b16 {%0,%1,%2,%3}, [%4];"
        : "=r"(r[0]), "=r"(r[1]), "=r"(r[2]), "=r"(r[3]) : "r"(a));
}
__device__ __forceinline__ void ldsm_x2(uint32_t* r, uint32_t a) {
    asm volatile(
        "ldmatrix.sync.aligned.m8n8.x2.shared.b16 {%0,%1}, [%2];"
        : "=r"(r[0]), "=r"(r[1]) : "r"(a));
}
__device__ __forceinline__ void ldsm_x2t(uint32_t* r, uint32_t a) {
    asm volatile(
        "ldmatrix.sync.aligned.m8n8.x2.trans.shared.b16 {%0,%1}, [%2];"
        : "=r"(r[0]), "=r"(r[1]) : "r"(a));
}
__device__ __forceinline__ void ldsm_x4t(uint32_t* r, uint32_t a) {
    asm volatile(
        "ldmatrix.sync.aligned.m8n8.x4.trans.shared.b16 {%0,%1,%2,%3}, [%4];"
        : "=r"(r[0]), "=r"(r[1]), "=r"(r[2]), "=r"(r[3]) : "r"(a));
}

__device__ __forceinline__ void cp_async16(uint32_t dst_smem, const void* src) {
    asm volatile("cp.async.cg.shared.global [%0], [%1], 16;" ::
                 "r"(dst_smem), "l"(src));
}
__device__ __forceinline__ void cp_commit() {
    asm volatile("cp.async.commit_group;");
}
template <int N>
__device__ __forceinline__ void cp_wait() {
    asm volatile("cp.async.wait_group %0;" :: "n"(N));
}

// ---------------- embedding (fp32 residual) --------------------------------
__global__ void embed_kernel(const int* __restrict__ ids,
                             const float* __restrict__ tok_emb,
                             const float* __restrict__ pos_emb,
                             float* __restrict__ x) {
    int idx = blockIdx.x * blockDim.x + threadIdx.x;
    if (idx >= CM * CD) return;
    int d = idx % CD;
    int bt = idx / CD;
    int t = bt % CT;
    x[idx] = tok_emb[(size_t)ids[bt] * CD + d] + pos_emb[t * CD + d];
}

// ---------------- qkv weight pack (+fp16 cvt): -> (L, D, 3*H*HS) -----------
__global__ void pack_qkv_kernel(const float* __restrict__ wq,
                                const float* __restrict__ wk,
                                const float* __restrict__ wv,
                                __half* __restrict__ wp) {
    const int PER = CL * CH * CD * CHS;
    int idx = blockIdx.x * blockDim.x + threadIdx.x;
    if (idx >= 3 * PER) return;
    int which = idx / PER;
    int r = idx % PER;
    int e = r % CHS;
    int d = (r / CHS) % CD;
    int h = (r / (CHS * CD)) % CH;
    int l = r / (CHS * CD * CH);
    const float* src = (which == 0) ? wq : (which == 1) ? wk : wv;
    wp[((size_t)l * CD + d) * (3 * CD) + which * CD + h * CHS + e] =
        __float2half_rn(src[r]);
}

// ---------------- merged weight fp16 convert (2 arrays per launch) ---------
__global__ void cvt_copy2_kernel(const float* __restrict__ s1,
                                 __half* __restrict__ d1, int n1,
                                 const float* __restrict__ s2,
                                 __half* __restrict__ d2, int n2) {
    int idx = blockIdx.x * blockDim.x + threadIdx.x;
    int q1 = n1 >> 2;
    if (idx < q1) {
        float4 v = ((const float4*)s1)[idx];
        uint2 o = make_uint2(pack_h2(v.x, v.y), pack_h2(v.z, v.w));
        *(uint2*)&d1[(size_t)idx * 4] = o;
    } else {
        int i2 = idx - q1;
        if (i2 * 4 < n2) {
            float4 v = ((const float4*)s2)[i2];
            uint2 o = make_uint2(pack_h2(v.x, v.y), pack_h2(v.z, v.w));
            *(uint2*)&d2[(size_t)i2 * 4] = o;
        }
    }
}

// ---------------- layernorm (fp16 output) -----------------------------------
__device__ __forceinline__ float warp_sum(float v) {
    #pragma unroll
    for (int o = 16; o; o >>= 1) v += __shfl_xor_sync(0xffffffffu, v, o);
    return v;
}

__global__ void ln_kernel(const float* __restrict__ x,
                          const float* __restrict__ g,
                          const float* __restrict__ b,
                          __half* __restrict__ out) {
    int row = blockIdx.x;
    int tid = threadIdx.x;
    const float4* xr = (const float4*)(x + (size_t)row * CD);
    float4 v = xr[tid];
    float s = v.x + v.y + v.z + v.w;
    float s2 = v.x * v.x + v.y * v.y + v.z * v.z + v.w * v.w;
    s = warp_sum(s);
    s2 = warp_sum(s2);
    __shared__ float shs[8], shs2[8];
    int w = tid >> 5, lane = tid & 31;
    if (lane == 0) { shs[w] = s; shs2[w] = s2; }
    __syncthreads();
    if (tid == 0) {
        float a = 0.f, a2 = 0.f;
        #pragma unroll
        for (int i = 0; i < 8; i++) { a += shs[i]; a2 += shs2[i]; }
        shs[0] = a; shs2[0] = a2;
    }
    __syncthreads();
    float mean = shs[0] * (1.f / CD);
    float var = shs2[0] * (1.f / CD) - mean * mean;
    float rstd = rsqrtf(var + 1e-5f);
    float4 gv = ((const float4*)g)[tid];
    float4 bv = ((const float4*)b)[tid];
    uint2 o = make_uint2(
        pack_h2((v.x - mean) * rstd * gv.x + bv.x, (v.y - mean) * rstd * gv.y + bv.y),
        pack_h2((v.z - mean) * rstd * gv.z + bv.z, (v.w - mean) * rstd * gv.w + bv.w));
    *(uint2*)&out[(size_t)row * CD + tid * 4] = o;
}

// ---------------- FP16 tensor-core GEMM (BK=32, 2 CTA/SM) -------------------
// C[M,N] = A[M,K] @ B[K,N] (+bias) (+res) (relu); C fp32 or fp16.
// Block 128x128, BK=32, 3-stage cp.async, 8 warps (2Mx4N), warp tile 64x32.
// A: ldmatrix.x4; B: ldmatrix.x4.trans (2 n-tiles per instruction).
// Grid: x = M-tile (fastest) for cross-M L2 reuse of B.
static constexpr int GSTAGES = 3;
static constexpr int A_PH = 40;            // halfs per A row (32 + 8 pad)
static constexpr int B_PH = 136;           // halfs per B row (128 + 8 pad)
static constexpr int G_ASZ = 128 * A_PH;   // halfs per A stage
static constexpr int G_BSZ = 32 * B_PH;    // halfs per B stage
static constexpr int GEMM_SMEM = GSTAGES * (G_ASZ + G_BSZ) * 2;  // ~56.8 KB

template <bool HAS_BIAS, bool HAS_RES, bool RELU, bool OUT_HALF>
__global__ __launch_bounds__(256, 2)
void f16_gemm(const __half* __restrict__ A, const __half* __restrict__ B,
              void* __restrict__ Cv, const float* __restrict__ bias,
              const float* __restrict__ res, int M, int N, int K) {
    extern __shared__ char smraw[];
    __half* As = (__half*)smraw;
    __half* Bs = As + GSTAGES * G_ASZ;

    const int tid = threadIdx.x;
    const int lane = tid & 31;
    const int warp = tid >> 5;
    const int wm = warp & 1;
    const int wn = warp >> 1;
    const int bm = blockIdx.x * 128;
    const int bn = blockIdx.y * 128;

    const int g = lane >> 2;
    const int tg = lane & 3;

    const uint32_t as_base = (uint32_t)__cvta_generic_to_shared(As);
    const uint32_t bs_base = (uint32_t)__cvta_generic_to_shared(Bs);

    // fragment base addresses (bytes)
    const uint32_t a_frag = as_base +
        (uint32_t)(((wm * 64 + (lane & 15)) * A_PH) + ((lane & 16) >> 1)) * 2;
    // x4.trans B: row kk+(lane&15), col wn*32 + 8*(lane>>4)
    const uint32_t b_frag = bs_base +
        (uint32_t)((lane & 15) * B_PH + wn * 32 + ((lane >> 4) << 3)) * 2;

    auto load_stage = [&](int s, int k0) {
        #pragma unroll
        for (int it = 0; it < 2; it++) {
            int idx = tid + it * 256;
            int row = idx >> 2, c = (idx & 3) * 8;
            cp_async16(as_base + (uint32_t)(s * G_ASZ + row * A_PH + c) * 2,
                       &A[(size_t)(bm + row) * K + k0 + c]);
        }
        #pragma unroll
        for (int it = 0; it < 2; it++) {
            int idx = tid + it * 256;
            int row = idx >> 4, c = (idx & 15) * 8;
            cp_async16(bs_base + (uint32_t)(s * G_BSZ + row * B_PH + c) * 2,
                       &B[(size_t)(k0 + row) * N + bn + c]);
        }
    };

    float acc[4][4][4];
    #pragma unroll
    for (int i = 0; i < 4; i++)
        #pragma unroll
        for (int j = 0; j < 4; j++)
            #pragma unroll
            for (int k = 0; k < 4; k++) acc[i][j][k] = 0.f;

    const int nk = K >> 5;
    #pragma unroll
    for (int s = 0; s < GSTAGES - 1; s++) {
        load_stage(s, s * 32);
        cp_commit();
    }
    cp_wait<GSTAGES - 2>();
    __syncthreads();

    for (int ks = 0; ks < nk; ks++) {
        const int buf = ks % GSTAGES;
        const int pre = ks + GSTAGES - 1;
        if (pre < nk) load_stage(pre % GSTAGES, pre * 32);
        cp_commit();

        const uint32_t a_st = a_frag + (uint32_t)(buf * G_ASZ) * 2;
        const uint32_t b_st = b_frag + (uint32_t)(buf * G_BSZ) * 2;
        #pragma unroll
        for (int kk = 0; kk < 32; kk += 16) {
            uint32_t af[4][4], bf[4][2];
            #pragma unroll
            for (int mi = 0; mi < 4; mi++)
                ldsm_x4(af[mi], a_st + (uint32_t)(mi * 16 * A_PH + kk) * 2);
            #pragma unroll
            for (int pr = 0; pr < 2; pr++) {
                uint32_t t[4];
                ldsm_x4t(t, b_st + (uint32_t)(kk * B_PH + pr * 16) * 2);
                bf[2 * pr][0] = t[0]; bf[2 * pr][1] = t[1];
                bf[2 * pr + 1][0] = t[2]; bf[2 * pr + 1][1] = t[3];
            }
            #pragma unroll
            for (int mi = 0; mi < 4; mi++)
                #pragma unroll
                for (int ni = 0; ni < 4; ni++)
                    mma_f16(acc[mi][ni], af[mi], bf[ni]);
        }

        cp_wait<GSTAGES - 2>();
        __syncthreads();
    }

    // epilogue
    #pragma unroll
    for (int mi = 0; mi < 4; mi++) {
        #pragma unroll
        for (int ni = 0; ni < 4; ni++) {
            const int col = bn + wn * 32 + ni * 8 + 2 * tg;
            #pragma unroll
            for (int half_ = 0; half_ < 2; half_++) {
                const int row = bm + wm * 64 + mi * 16 + g + half_ * 8;
                float vx = acc[mi][ni][half_ * 2 + 0];
                float vy = acc[mi][ni][half_ * 2 + 1];
                if (HAS_BIAS) { vx += bias[col]; vy += bias[col + 1]; }
                if (HAS_RES) {
                    const float2 r = *(const float2*)&res[(size_t)row * N + col];
                    vx += r.x; vy += r.y;
                }
                if (RELU) { vx = fmaxf(vx, 0.f); vy = fmaxf(vy, 0.f); }
                if (OUT_HALF) {
                    *(uint32_t*)&((__half*)Cv)[(size_t)row * N + col] = pack_h2(vx, vy);
                } else {
                    *(float2*)&((float*)Cv)[(size_t)row * N + col] = make_float2(vx, vy);
                }
            }
        }
    }
}

// ---------------- fp16 tensor-core flash attention --------------------------
static constexpr int AQP = 72;
static constexpr int ATT_SMEM = (128 + 64 + 64) * AQP * 2;

__global__ __launch_bounds__(256, 2)
void attn_f16_kernel(const __half* __restrict__ qkv, __half* __restrict__ out) {
    extern __shared__ char smraw[];
    __half* Qs = (__half*)smraw;          // [128][AQP]
    __half* Ks = Qs + 128 * AQP;          // [64][AQP]
    __half* Vs = Ks + 64 * AQP;           // [64][AQP]

    const int qt = blockIdx.x;
    const int h = blockIdx.y;
    const int b = blockIdx.z;
    const int tid = threadIdx.x;
    const int lane = tid & 31;
    const int warp = tid >> 5;
    const int g = lane >> 2;
    const int tg = lane & 3;
    const int rw = warp * 16;

    const size_t base = (size_t)(b * CT) * (3 * CD) + h * CHS;

    #pragma unroll
    for (int it = 0; it < 4; it++) {
        int idx = tid + it * 256;
        int r = idx >> 3, c = (idx & 7) * 8;
        *(uint4*)&Qs[r * AQP + c] =
            *(const uint4*)&qkv[base + (size_t)(qt * 128 + r) * (3 * CD) + c];
    }

    const uint32_t qs_u = (uint32_t)__cvta_generic_to_shared(Qs);
    const uint32_t ks_u = (uint32_t)__cvta_generic_to_shared(Ks);
    const uint32_t vs_u = (uint32_t)__cvta_generic_to_shared(Vs);

    const uint32_t q_frag =
        qs_u + (uint32_t)(((rw + (lane & 15)) * AQP) + ((lane & 16) >> 1)) * 2;
    const uint32_t k_fragbase =
        ks_u + (uint32_t)((lane & 7) * AQP + (lane & 8)) * 2;
    const uint32_t v_fragbase =
        vs_u + (uint32_t)((lane & 15) * AQP) * 2;

    const float scale = 0.03125f;  // 1/sqrt(1024): reference scales by d_model
    const int rowq0 = qt * 128 + rw + g;
    const int rowq1 = rowq0 + 8;

    float m0 = -1e30f, m1 = -1e30f, l0 = 0.f, l1 = 0.f;
    float acc_o[8][4];
    #pragma unroll
    for (int i = 0; i < 8; i++)
        #pragma unroll
        for (int j = 0; j < 4; j++) acc_o[i][j] = 0.f;

    const int nst = 2 * qt + 2;
    for (int st = 0; st < nst; st++) {
        __syncthreads();
        #pragma unroll
        for (int it = 0; it < 2; it++) {
            int idx = tid + it * 256;
            int r = idx >> 3, c = (idx & 7) * 8;
            size_t ga = base + (size_t)(st * 64 + r) * (3 * CD);
            *(uint4*)&Ks[r * AQP + c] = *(const uint4*)&qkv[ga + CD + c];
            *(uint4*)&Vs[r * AQP + c] = *(const uint4*)&qkv[ga + 2 * CD + c];
        }
        __syncthreads();

        float acc_s[8][4];
        #pragma unroll
        for (int i = 0; i < 8; i++)
            #pragma unroll
            for (int j = 0; j < 4; j++) acc_s[i][j] = 0.f;
        #pragma unroll
        for (int kk = 0; kk < 64; kk += 16) {
            uint32_t af[4];
            ldsm_x4(af, q_frag + (uint32_t)kk * 2);
            #pragma unroll
            for (int ni = 0; ni < 8; ni++) {
                uint32_t bf[2];
                ldsm_x2(bf, k_fragbase + (uint32_t)(ni * 8 * AQP + kk) * 2);
                mma_f16(acc_s[ni], af, bf);
            }
        }

        float rmax0 = -1e30f, rmax1 = -1e30f;
        #pragma unroll
        for (int ni = 0; ni < 8; ni++) {
            const int c0 = st * 64 + ni * 8 + 2 * tg;
            float v0 = acc_s[ni][0] * scale; if (c0 > rowq0) v0 = -1e30f;
            float v1 = acc_s[ni][1] * scale; if (c0 + 1 > rowq0) v1 = -1e30f;
            float v2 = acc_s[ni][2] * scale; if (c0 > rowq1) v2 = -1e30f;
            float v3 = acc_s[ni][3] * scale; if (c0 + 1 > rowq1) v3 = -1e30f;
            acc_s[ni][0] = v0; acc_s[ni][1] = v1;
            acc_s[ni][2] = v2; acc_s[ni][3] = v3;
            rmax0 = fmaxf(rmax0, fmaxf(v0, v1));
            rmax1 = fmaxf(rmax1, fmaxf(v2, v3));
        }
        #pragma unroll
        for (int off = 1; off < 4; off <<= 1) {
            rmax0 = fmaxf(rmax0, __shfl_xor_sync(0xffffffffu, rmax0, off));
            rmax1 = fmaxf(rmax1, __shfl_xor_sync(0xffffffffu, rmax1, off));
        }

        const float mn0 = fmaxf(m0, rmax0), mn1 = fmaxf(m1, rmax1);
        const float sc0 = __expf(m0 - mn0), sc1 = __expf(m1 - mn1);
        m0 = mn0; m1 = mn1;
        float rs0 = 0.f, rs1 = 0.f;
        #pragma unroll
        for (int ni = 0; ni < 8; ni++) {
            float p0 = __expf(acc_s[ni][0] - mn0);
            float p1 = __expf(acc_s[ni][1] - mn0);
            float p2 = __expf(acc_s[ni][2] - mn1);
            float p3 = __expf(acc_s[ni][3] - mn1);
            acc_s[ni][0] = p0; acc_s[ni][1] = p1;
            acc_s[ni][2] = p2; acc_s[ni][3] = p3;
            rs0 += p0 + p1; rs1 += p2 + p3;
        }
        #pragma unroll
        for (int off = 1; off < 4; off <<= 1) {
            rs0 += __shfl_xor_sync(0xffffffffu, rs0, off);
            rs1 += __shfl_xor_sync(0xffffffffu, rs1, off);
        }
        l0 = l0 * sc0 + rs0;
        l1 = l1 * sc1 + rs1;
        #pragma unroll
        for (int ni = 0; ni < 8; ni++) {
            acc_o[ni][0] *= sc0; acc_o[ni][1] *= sc0;
            acc_o[ni][2] *= sc1; acc_o[ni][3] *= sc1;
        }

        #pragma unroll
        for (int j = 0; j < 4; j++) {
            uint32_t pa[4];
            pa[0] = pack_h2(acc_s[2 * j][0], acc_s[2 * j][1]);
            pa[1] = pack_h2(acc_s[2 * j][2], acc_s[2 * j][3]);
            pa[2] = pack_h2(acc_s[2 * j + 1][0], acc_s[2 * j + 1][1]);
            pa[3] = pack_h2(acc_s[2 * j + 1][2], acc_s[2 * j + 1][3]);
            #pragma unroll
            for (int ni = 0; ni < 8; ni++) {
                uint32_t bf[2];
                ldsm_x2t(bf, v_fragbase + (uint32_t)(j * 16 * AQP + ni * 8) * 2);
                mma_f16(acc_o[ni], pa, bf);
            }
        }
    }

    const float inv0 = 1.f / l0, inv1 = 1.f / l1;
    #pragma unroll
    for (int ni = 0; ni < 8; ni++) {
        const int col = h * CHS + ni * 8 + 2 * tg;
        *(uint32_t*)&out[(size_t)(b * CT + rowq0) * CD + col] =
            pack_h2(acc_o[ni][0] * inv0, acc_o[ni][1] * inv0);
        *(uint32_t*)&out[(size_t)(b * CT + rowq1) * CD + col] =
            pack_h2(acc_o[ni][2] * inv1, acc_o[ni][3] * inv1);
    }
}

// ---------------- host orchestration --------------------------------------
extern "C" void kernel_launch(void* const* d_in, const int* in_sizes, int n_in,
                              void* d_out, int out_size) {
    const int*   token_ids = (const int*)d_in[0];
    const float* tok_emb   = (const float*)d_in[1];
    const float* pos_emb   = (const float*)d_in[2];
    const float* wq        = (const float*)d_in[3];
    const float* wk        = (const float*)d_in[4];
    const float* wv        = (const float*)d_in[5];
    const float* w_proj    = (const float*)d_in[6];
    const float* b_proj    = (const float*)d_in[7];
    const float* ln1_g     = (const float*)d_in[8];
    const float* ln1_b     = (const float*)d_in[9];
    const float* ln2_g     = (const float*)d_in[10];
    const float* ln2_b     = (const float*)d_in[11];
    const float* w1        = (const float*)d_in[12];
    const float* b1        = (const float*)d_in[13];
    const float* w2        = (const float*)d_in[14];
    const float* b2        = (const float*)d_in[15];
    const float* lnf_g     = (const float*)d_in[16];
    const float* lnf_b     = (const float*)d_in[17];
    const float* w_out     = (const float*)d_in[18];
    const float* b_out     = (const float*)d_in[19];
    float* out = (float*)d_out;

    float* x;
    __half *hbuf, *qkv, *act, *wpack, *wproj_h, *w1_h, *w2_h, *wout_h;
    cudaGetSymbolAddress((void**)&x, g_x);
    cudaGetSymbolAddress((void**)&hbuf, g_h);
    cudaGetSymbolAddress((void**)&qkv, g_qkv);
    cudaGetSymbolAddress((void**)&act, g_act);
    cudaGetSymbolAddress((void**)&wpack, g_wpack);
    cudaGetSymbolAddress((void**)&wproj_h, g_wproj_h);
    cudaGetSymbolAddress((void**)&w1_h, g_w1_h);
    cudaGetSymbolAddress((void**)&w2_h, g_w2_h);
    cudaGetSymbolAddress((void**)&wout_h, g_wout_h);

    cudaFuncSetAttribute(attn_f16_kernel,
                         cudaFuncAttributeMaxDynamicSharedMemorySize, ATT_SMEM);
    cudaFuncSetAttribute(f16_gemm<false, false, false, true>,
                         cudaFuncAttributeMaxDynamicSharedMemorySize, GEMM_SMEM);
    cudaFuncSetAttribute(f16_gemm<true, true, false, false>,
                         cudaFuncAttributeMaxDynamicSharedMemorySize, GEMM_SMEM);
    cudaFuncSetAttribute(f16_gemm<true, false, true, true>,
                         cudaFuncAttributeMaxDynamicSharedMemorySize, GEMM_SMEM);
    cudaFuncSetAttribute(f16_gemm<true, false, false, false>,
                         cudaFuncAttributeMaxDynamicSharedMemorySize, GEMM_SMEM);

    // 1) embedding
    {
        int n = CM * CD;
        embed_kernel<<<(n + 255) / 256, 256>>>(token_ids, tok_emb, pos_emb, x);
    }
    // 2) weight prep (fp16 convert)
    {
        int n = 3 * CL * CH * CD * CHS;
        pack_qkv_kernel<<<(n + 255) / 256, 256>>>(wq, wk, wv, wpack);
    }
    {
        int n1 = CL * CD * CD, n2 = CL * CD * CFF;
        int tot = (n1 + n2) / 4;
        cvt_copy2_kernel<<<(tot + 255) / 256, 256>>>(w_proj, wproj_h, n1,
                                                     w1, w1_h, n2);
        int n3 = CL * CFF * CD, n4 = CD * CV;
        tot = (n3 + n4) / 4;
        cvt_copy2_kernel<<<(tot + 255) / 256, 256>>>(w2, w2_h, n3,
                                                     w_out, wout_h, n4);
    }

    dim3 attn_grid(CT / 128, CH, CB);

    for (int l = 0; l < CL; l++) {
        // ln1 -> h (fp16)
        ln_kernel<<<CM, 256>>>(x, ln1_g + l * CD, ln1_b + l * CD, hbuf);
        // qkv = h @ wpack[l]   (4096 x 3072 x 1024), fp16 out
        {
            dim3 grid(CM / 128, 3 * CD / 128);
            f16_gemm<false, false, false, true><<<grid, 256, GEMM_SMEM>>>(
                hbuf, wpack + (size_t)l * CD * 3 * CD, qkv, nullptr, nullptr,
                CM, 3 * CD, CD);
        }
        // attention -> h (fp16 flash)
        attn_f16_kernel<<<attn_grid, 256, ATT_SMEM>>>(qkv, hbuf);
        // x = x + h @ w_proj[l] + b_proj[l]  (fp32 out + residual)
        {
            dim3 grid(CM / 128, CD / 128);
            f16_gemm<true, true, false, false><<<grid, 256, GEMM_SMEM>>>(
                hbuf, wproj_h + (size_t)l * CD * CD, x, b_proj + l * CD, x,
                CM, CD, CD);
        }
        // ln2 -> h (fp16)
        ln_kernel<<<CM, 256>>>(x, ln2_g + l * CD, ln2_b + l * CD, hbuf);
        // act = relu(h @ w1[l] + b1[l])  (fp16 out)
        {
            dim3 grid(CM / 128, CFF / 128);
            f16_gemm<true, false, true, true><<<grid, 256, GEMM_SMEM>>>(
                hbuf, w1_h + (size_t)l * CD * CFF, act, b1 + (size_t)l * CFF, nullptr,
                CM, CFF, CD);
        }
        // x = x + act @ w2[l] + b2[l]  (fp32 out + residual)
        {
            dim3 grid(CM / 128, CD / 128);
            f16_gemm<true, true, false, false><<<grid, 256, GEMM_SMEM>>>(
                act, w2_h + (size_t)l * CFF * CD, x, b2 + l * CD, x,
                CM, CD, CFF);
        }
    }

    // final ln -> h (fp16)
    ln_kernel<<<CM, 256>>>(x, lnf_g, lnf_b, hbuf);
    // logits = h @ w_out + b_out   (4096 x 32000 x 1024), fp32 out
    {
        dim3 grid(CM / 128, CV / 128);
        f16_gemm<true, false, false, false><<<grid, 256, GEMM_SMEM>>>(
            hbuf, wout_h, out, b_out, nullptr, CM, CV, CD);
    }
}